// round 1
// baseline (speedup 1.0000x reference)
#include <cuda_runtime.h>

// Problem constants
#define BB 16
#define TT 4096
#define DD 768
#define NBOX 1024
#define MAXB 128
#define DDETR 256
#define VIS_ELEMS (BB*MAXB*DD)   // 1,572,864
#define MASK_ELEMS (BB*MAXB)     // 2,048
#define NC 64                    // t-chunks for mean reduction

// ---------------- scratch (device globals; no allocations allowed) ----------
__device__ __align__(16) float g_partial[BB*NC*DD];
__device__ __align__(16) float g_x[BB*DD];
__device__ __align__(16) float g_h1t[BB*DD];
__device__ __align__(16) float g_h1d[BB*DD];
__device__ __align__(16) float g_xt[BB*DD];
__device__ __align__(16) float g_fm1[NBOX*DD];
__device__ __align__(16) float g_fm[NBOX*DD];
__device__ int g_pos[NBOX];

// ---------------- zero vis_output region ------------------------------------
__global__ void zero_vis_kernel(float4* __restrict__ out) {
    const int n4 = VIS_ELEMS / 4;
    for (int i = blockIdx.x * blockDim.x + threadIdx.x; i < n4;
         i += gridDim.x * blockDim.x)
        out[i] = make_float4(0.f, 0.f, 0.f, 0.f);
}

// ---------------- mean over T: pass 1 (partial sums over 64-row chunks) -----
// grid = BB*NC blocks, block = 192 threads (= DD/4 float4 lanes)
__global__ void mean_partial_kernel(const float* __restrict__ in) {
    int b = blockIdx.x >> 6;
    int c = blockIdx.x & 63;
    const float4* p = reinterpret_cast<const float4*>(
        in + ((size_t)b * TT + (size_t)c * 64) * DD) + threadIdx.x;
    float4 acc = make_float4(0.f, 0.f, 0.f, 0.f);
    #pragma unroll 8
    for (int r = 0; r < 64; r++) {
        float4 v = p[(size_t)r * (DD / 4)];
        acc.x += v.x; acc.y += v.y; acc.z += v.z; acc.w += v.w;
    }
    reinterpret_cast<float4*>(g_partial + ((size_t)b * NC + c) * DD)[threadIdx.x] = acc;
}

// ---------------- mean over T: pass 2 (reduce chunks, scale by 1/T) ---------
// grid = 12 blocks x 256 threads = 3072 = BB * DD/4
__global__ void mean_final_kernel() {
    int i = blockIdx.x * blockDim.x + threadIdx.x;
    int b  = i / (DD / 4);
    int c4 = i % (DD / 4);
    const float4* p = reinterpret_cast<const float4*>(g_partial)
                      + (size_t)b * NC * (DD / 4) + c4;
    float4 acc = make_float4(0.f, 0.f, 0.f, 0.f);
    #pragma unroll 8
    for (int c = 0; c < NC; c++) {
        float4 v = p[(size_t)c * (DD / 4)];
        acc.x += v.x; acc.y += v.y; acc.z += v.z; acc.w += v.w;
    }
    const float s = 1.0f / (float)TT;
    acc.x *= s; acc.y *= s; acc.z *= s; acc.w *= s;
    reinterpret_cast<float4*>(g_x)[(size_t)b * (DD / 4) + c4] = acc;
}

// ---------------- small MLP layer (both t- and d- branches in one launch) ---
// layer 0: h1t = relu(x@t1w^T+t1b), h1d = relu(x@d1w^T+d1b)
// layer 1: xt = h1t@t2w^T+t2b,     ret_x = h1d@d2w^T+d2b (to d_out)
// grid = 192 blocks (96 per branch), block = 256 (8 warps, 1 warp = 1 out col)
__global__ void small_gemm_kernel(int layer,
                                  const float* __restrict__ w0, const float* __restrict__ b0,
                                  const float* __restrict__ w1, const float* __restrict__ b1,
                                  float* __restrict__ retx_out) {
    __shared__ float xs[BB * DD];   // 48 KB
    int branch = blockIdx.x / 96;
    const float* in   = (layer == 0) ? g_x : (branch ? g_h1d : g_h1t);
    const float* w    = branch ? w1 : w0;
    const float* bias = branch ? b1 : b0;
    float* out        = (layer == 0) ? (branch ? g_h1d : g_h1t)
                                     : (branch ? retx_out : g_xt);
    for (int i = threadIdx.x; i < BB * DD; i += 256) xs[i] = in[i];
    __syncthreads();

    int warp = threadIdx.x >> 5, lane = threadIdx.x & 31;
    int j = (blockIdx.x % 96) * 8 + warp;
    const float* wr = w + (size_t)j * DD;
    float acc[BB];
    #pragma unroll
    for (int b = 0; b < BB; b++) acc[b] = 0.f;

    for (int k = lane; k < DD; k += 32) {
        float wv = wr[k];
        #pragma unroll
        for (int b = 0; b < BB; b++)
            acc[b] = fmaf(wv, xs[b * DD + k], acc[b]);
    }
    #pragma unroll
    for (int b = 0; b < BB; b++) {
        #pragma unroll
        for (int off = 16; off > 0; off >>= 1)
            acc[b] += __shfl_xor_sync(0xFFFFFFFFu, acc[b], off);
    }
    if (lane == 0) {
        float bb = bias[j];
        #pragma unroll
        for (int b = 0; b < BB; b++) {
            float v = acc[b] + bb;
            if (layer == 0) v = fmaxf(v, 0.f);
            out[b * DD + j] = v;
        }
    }
}

// ---------------- segment metadata: counts, pos, att_mask -------------------
// 1 block, NBOX threads. img is sorted, so pos[n] = n - offset[img[n]].
__global__ void meta_kernel(const int* __restrict__ bboxes,
                            float* __restrict__ att_mask_out) {
    __shared__ int counts[BB];
    __shared__ int offs[BB];
    int t = threadIdx.x;
    if (t < BB) counts[t] = 0;
    __syncthreads();
    int im = bboxes[t * 5];
    atomicAdd(&counts[im], 1);
    __syncthreads();
    if (t == 0) {
        int s = 0;
        for (int b = 0; b < BB; b++) { offs[b] = s; s += counts[b]; }
    }
    __syncthreads();
    g_pos[t] = t - offs[im];
    for (int i = t; i < BB * MAXB; i += NBOX) {
        int b = i / MAXB, m = i % MAXB;
        att_mask_out[i] = (m < counts[b]) ? 1.0f : 0.0f;
    }
}

// ---------------- tiled GEMM 1: fm1 = relu(features[:,1:] @ m1w^T + m1b) ----
// M=1024, N=768, K=256. BM=BN=64, BK=32, 256 threads, 4x4 microtile.
__global__ void gemm_fm1_kernel(const float* __restrict__ feat,
                                const float* __restrict__ w,
                                const float* __restrict__ bias) {
    __shared__ float As[32][68];
    __shared__ float Bs[32][68];
    int bm = blockIdx.x, bn = blockIdx.y;
    int tid = threadIdx.x;
    int tr = tid >> 4, tc = tid & 15;
    float acc[4][4];
    #pragma unroll
    for (int i = 0; i < 4; i++)
        #pragma unroll
        for (int j = 0; j < 4; j++) acc[i][j] = 0.f;

    for (int kt = 0; kt < DDETR; kt += 32) {
        // A: features rows bm*64..+64, cols 1+kt..+32 (stride 257, scalar loads)
        {
            int kk = tid & 31, r0 = tid >> 5;
            #pragma unroll
            for (int i = 0; i < 8; i++) {
                int r = r0 + i * 8;
                As[kk][r] = feat[(size_t)(bm * 64 + r) * (DDETR + 1) + 1 + kt + kk];
            }
        }
        // B: w rows bn*64..+64, cols kt..+32 (float4)
        {
            #pragma unroll
            for (int i = 0; i < 2; i++) {
                int f = tid + i * 256;
                int r = f >> 3, c = (f & 7) * 4;
                float4 v = *reinterpret_cast<const float4*>(
                    &w[(size_t)(bn * 64 + r) * DDETR + kt + c]);
                Bs[c + 0][r] = v.x; Bs[c + 1][r] = v.y;
                Bs[c + 2][r] = v.z; Bs[c + 3][r] = v.w;
            }
        }
        __syncthreads();
        #pragma unroll
        for (int k = 0; k < 32; k++) {
            float4 av = *reinterpret_cast<const float4*>(&As[k][tr * 4]);
            float4 bv = *reinterpret_cast<const float4*>(&Bs[k][tc * 4]);
            float a[4] = {av.x, av.y, av.z, av.w};
            float b[4] = {bv.x, bv.y, bv.z, bv.w};
            #pragma unroll
            for (int i = 0; i < 4; i++)
                #pragma unroll
                for (int j = 0; j < 4; j++)
                    acc[i][j] = fmaf(a[i], b[j], acc[i][j]);
        }
        __syncthreads();
    }
    int row0 = bm * 64 + tr * 4, col0 = bn * 64 + tc * 4;
    #pragma unroll
    for (int i = 0; i < 4; i++)
        #pragma unroll
        for (int j = 0; j < 4; j++) {
            float v = acc[i][j] + bias[col0 + j];
            g_fm1[(size_t)(row0 + i) * DD + col0 + j] = fmaxf(v, 0.f);
        }
}

// ---------------- tiled GEMM 2: fm = fm1 @ m2w^T + m2b ----------------------
// M=1024, N=768, K=768
__global__ void gemm_fm2_kernel(const float* __restrict__ w,
                                const float* __restrict__ bias) {
    __shared__ float As[32][68];
    __shared__ float Bs[32][68];
    int bm = blockIdx.x, bn = blockIdx.y;
    int tid = threadIdx.x;
    int tr = tid >> 4, tc = tid & 15;
    float acc[4][4];
    #pragma unroll
    for (int i = 0; i < 4; i++)
        #pragma unroll
        for (int j = 0; j < 4; j++) acc[i][j] = 0.f;

    for (int kt = 0; kt < DD; kt += 32) {
        #pragma unroll
        for (int i = 0; i < 2; i++) {
            int f = tid + i * 256;
            int r = f >> 3, c = (f & 7) * 4;
            float4 va = *reinterpret_cast<const float4*>(
                &g_fm1[(size_t)(bm * 64 + r) * DD + kt + c]);
            As[c + 0][r] = va.x; As[c + 1][r] = va.y;
            As[c + 2][r] = va.z; As[c + 3][r] = va.w;
            float4 vb = *reinterpret_cast<const float4*>(
                &w[(size_t)(bn * 64 + r) * DD + kt + c]);
            Bs[c + 0][r] = vb.x; Bs[c + 1][r] = vb.y;
            Bs[c + 2][r] = vb.z; Bs[c + 3][r] = vb.w;
        }
        __syncthreads();
        #pragma unroll
        for (int k = 0; k < 32; k++) {
            float4 av = *reinterpret_cast<const float4*>(&As[k][tr * 4]);
            float4 bv = *reinterpret_cast<const float4*>(&Bs[k][tc * 4]);
            float a[4] = {av.x, av.y, av.z, av.w};
            float b[4] = {bv.x, bv.y, bv.z, bv.w};
            #pragma unroll
            for (int i = 0; i < 4; i++)
                #pragma unroll
                for (int j = 0; j < 4; j++)
                    acc[i][j] = fmaf(a[i], b[j], acc[i][j]);
        }
        __syncthreads();
    }
    int row0 = bm * 64 + tr * 4, col0 = bn * 64 + tc * 4;
    #pragma unroll
    for (int i = 0; i < 4; i++)
        #pragma unroll
        for (int j = 0; j < 4; j++)
            g_fm[(size_t)(row0 + i) * DD + col0 + j] = acc[i][j] + bias[col0 + j];
}

// ---------------- tiled GEMM 3 + scatter epilogue ---------------------------
// h[n] = [xt[img[n]] | fm[n]] @ pw^T + pb, written to vis_output[img[n], pos[n]]
// M=1024, N=768, K=1536 (first 768 gathered from xt, last 768 from fm)
__global__ void gemm_h_kernel(const int* __restrict__ bboxes,
                              const float* __restrict__ pw,
                              const float* __restrict__ pb,
                              float* __restrict__ out_vis) {
    __shared__ float As[32][68];
    __shared__ float Bs[32][68];
    __shared__ int simg[64];
    int bm = blockIdx.x, bn = blockIdx.y;
    int tid = threadIdx.x;
    int tr = tid >> 4, tc = tid & 15;
    if (tid < 64) simg[tid] = bboxes[(bm * 64 + tid) * 5];
    __syncthreads();

    float acc[4][4];
    #pragma unroll
    for (int i = 0; i < 4; i++)
        #pragma unroll
        for (int j = 0; j < 4; j++) acc[i][j] = 0.f;

    for (int kt = 0; kt < 2 * DD; kt += 32) {
        #pragma unroll
        for (int i = 0; i < 2; i++) {
            int f = tid + i * 256;
            int r = f >> 3, c = (f & 7) * 4;
            int kg = kt + c;
            const float* src = (kg < DD)
                ? (g_xt + (size_t)simg[r] * DD + kg)
                : (g_fm + (size_t)(bm * 64 + r) * DD + (kg - DD));
            float4 va = *reinterpret_cast<const float4*>(src);
            As[c + 0][r] = va.x; As[c + 1][r] = va.y;
            As[c + 2][r] = va.z; As[c + 3][r] = va.w;
            float4 vb = *reinterpret_cast<const float4*>(
                &pw[(size_t)(bn * 64 + r) * (2 * DD) + kt + c]);
            Bs[c + 0][r] = vb.x; Bs[c + 1][r] = vb.y;
            Bs[c + 2][r] = vb.z; Bs[c + 3][r] = vb.w;
        }
        __syncthreads();
        #pragma unroll
        for (int k = 0; k < 32; k++) {
            float4 av = *reinterpret_cast<const float4*>(&As[k][tr * 4]);
            float4 bv = *reinterpret_cast<const float4*>(&Bs[k][tc * 4]);
            float a[4] = {av.x, av.y, av.z, av.w};
            float b[4] = {bv.x, bv.y, bv.z, bv.w};
            #pragma unroll
            for (int i = 0; i < 4; i++)
                #pragma unroll
                for (int j = 0; j < 4; j++)
                    acc[i][j] = fmaf(a[i], b[j], acc[i][j]);
        }
        __syncthreads();
    }
    int row0 = bm * 64 + tr * 4, col0 = bn * 64 + tc * 4;
    float bb[4];
    #pragma unroll
    for (int j = 0; j < 4; j++) bb[j] = pb[col0 + j];
    #pragma unroll
    for (int i = 0; i < 4; i++) {
        int n = row0 + i;
        int p = g_pos[n];
        int im = simg[tr * 4 + i];
        if (p < MAXB) {
            float* dst = out_vis + ((size_t)im * MAXB + p) * DD + col0;
            #pragma unroll
            for (int j = 0; j < 4; j++)
                dst[j] = acc[i][j] + bb[j];
        }
    }
}

// ---------------- launch -----------------------------------------------------
extern "C" void kernel_launch(void* const* d_in, const int* in_sizes, int n_in,
                              void* d_out, int out_size) {
    (void)in_sizes; (void)n_in; (void)out_size;
    const float* inputs   = (const float*)d_in[0];
    const int*   bboxes   = (const int*)  d_in[1];
    const float* features = (const float*)d_in[2];
    const float* t1w = (const float*)d_in[3],  *t1b = (const float*)d_in[4];
    const float* t2w = (const float*)d_in[5],  *t2b = (const float*)d_in[6];
    const float* d1w = (const float*)d_in[7],  *d1b = (const float*)d_in[8];
    const float* d2w = (const float*)d_in[9],  *d2b = (const float*)d_in[10];
    const float* m1w = (const float*)d_in[11], *m1b = (const float*)d_in[12];
    const float* m2w = (const float*)d_in[13], *m2b = (const float*)d_in[14];
    const float* pw  = (const float*)d_in[15], *pb  = (const float*)d_in[16];

    float* out      = (float*)d_out;
    float* out_vis  = out;
    float* out_mask = out + VIS_ELEMS;
    float* out_retx = out + VIS_ELEMS + MASK_ELEMS;

    zero_vis_kernel<<<512, 256>>>((float4*)out_vis);
    mean_partial_kernel<<<BB * NC, 192>>>(inputs);
    mean_final_kernel<<<12, 256>>>();
    small_gemm_kernel<<<192, 256>>>(0, t1w, t1b, d1w, d1b, nullptr);
    small_gemm_kernel<<<192, 256>>>(1, t2w, t2b, d2w, d2b, out_retx);
    meta_kernel<<<1, NBOX>>>(bboxes, out_mask);
    gemm_fm1_kernel<<<dim3(16, 12), 256>>>(features, m1w, m1b);
    gemm_fm2_kernel<<<dim3(16, 12), 256>>>(m2w, m2b);
    gemm_h_kernel<<<dim3(16, 12), 256>>>(bboxes, pw, pb, out_vis);
}